// round 9
// baseline (speedup 1.0000x reference)
#include <cuda_runtime.h>
#include <cstdint>

#define T_STEPS 50
#define NB2 32          // fallback scan CTAs
#define CL 16           // cluster CTAs; each owns 16 of 256 hidden units

typedef unsigned long long ull;

// ---------------- scratch (device globals; no allocation) ----------------
__device__ float    g_pre[T_STEPS * 768];   // Wih_low[:, :256]@x_t + bih_low
__device__ float    g_xc [T_STEPS * 256];   // concat(f_v, f_m)
__device__ float    g_Lout[T_STEPS * 256];  // h1 per step
__device__ float    g_h1[2][256];           // fallback state
__device__ float    g_h2[2][256];
__device__ unsigned g_slots[NB2];           // fallback barrier slots

// ---------------- helpers ----------------
__device__ __forceinline__ float warpsum(float v) {
    v += __shfl_xor_sync(0xffffffffu, v, 16);
    v += __shfl_xor_sync(0xffffffffu, v, 8);
    v += __shfl_xor_sync(0xffffffffu, v, 4);
    v += __shfl_xor_sync(0xffffffffu, v, 2);
    v += __shfl_xor_sync(0xffffffffu, v, 1);
    return v;
}
__device__ __forceinline__ float eluf(float x) { return x > 0.f ? x : expm1f(x); }
__device__ __forceinline__ float sigf(float x) { return 1.f / (1.f + expf(-x)); }
__device__ __forceinline__ float dot4(float4 a, float4 b) {
    return a.x * b.x + a.y * b.y + a.z * b.z + a.w * b.w;
}
__device__ __forceinline__ uint32_t s2u(const void* p) {
    uint32_t a;
    asm("{ .reg .u64 t; cvta.to.shared.u64 t, %1; cvt.u32.u64 %0, t; }"
        : "=r"(a) : "l"(p));
    return a;
}
__device__ __forceinline__ uint32_t mapa_rk(uint32_t laddr, int rk) {
    uint32_t ra;
    asm volatile("mapa.shared::cluster.u32 %0, %1, %2;"
                 : "=r"(ra) : "r"(laddr), "r"(rk));
    return ra;
}
__device__ __forceinline__ void dsm_store(uint32_t ra, float v) {
    asm volatile("st.shared::cluster.f32 [%0], %1;" :: "r"(ra), "f"(v) : "memory");
}
#define CLUSTER_ARRIVE() asm volatile("barrier.cluster.arrive.aligned;" ::: "memory")
#define CLUSTER_WAIT()   asm volatile("barrier.cluster.wait.aligned;"   ::: "memory")

// packed f32x2 ops (sm_103a)
__device__ __forceinline__ ull pack2(float lo, float hi) {
    ull r; asm("mov.b64 %0, {%1, %2};" : "=l"(r) : "f"(lo), "f"(hi)); return r;
}
__device__ __forceinline__ ull fmul2(ull a, ull b) {
    ull d; asm("mul.rn.f32x2 %0, %1, %2;" : "=l"(d) : "l"(a), "l"(b)); return d;
}
__device__ __forceinline__ ull ffma2(ull a, ull b, ull c) {
    ull d; asm("fma.rn.f32x2 %0, %1, %2, %3;" : "=l"(d) : "l"(a), "l"(b), "l"(c));
    return d;
}
__device__ __forceinline__ float dotred(ull acc) {
    float lo, hi; asm("mov.b64 {%0, %1}, %2;" : "=f"(lo), "=f"(hi) : "l"(acc));
    return lo + hi;
}

// fallback epoch barrier (proven)
__device__ __forceinline__ void gridbar(unsigned epoch, int tid, int cta) {
    __syncthreads();
    if (tid == 0)
        asm volatile("st.release.gpu.global.u32 [%0], %1;"
                     :: "l"(g_slots + cta), "r"(epoch) : "memory");
    if (tid < 32) {
        unsigned v;
        do {
            asm volatile("ld.acquire.gpu.global.u32 %0, [%1];"
                         : "=r"(v) : "l"(g_slots + tid) : "memory");
        } while (__any_sync(0xffffffffu, v < epoch));
    }
    __syncthreads();
}

// ---------------- k1a: f_v / f_m -> g_xc, + fallback state init ----------------
__global__ void __launch_bounds__(256) k1a_feat(
    const float* __restrict__ v0, const float* __restrict__ m0,
    const float* __restrict__ W1v, const float* __restrict__ b1v,
    const float* __restrict__ W1m, const float* __restrict__ b1m)
{
    int t = blockIdx.x, q = blockIdx.y;
    int tid = threadIdx.x, warp = tid >> 5, lane = tid & 31;
    __shared__ __align__(16) float xv[768];
    for (int i = tid; i < 768; i += 256) xv[i] = v0[t * 768 + i];
    __syncthreads();

    const float4* xv4 = (const float4*)xv;
    float p[4];
#pragma unroll
    for (int u = 0; u < 4; u++) {
        int i = q * 32 + warp + 8 * u;
        const float4* w = (const float4*)(W1v + i * 768);
        float s = 0.f;
#pragma unroll
        for (int k = 0; k < 6; k++)
            s += dot4(__ldg(w + lane + 32 * k), xv4[lane + 32 * k]);
        p[u] = s;
    }
#pragma unroll
    for (int u = 0; u < 4; u++) {
        p[u] = warpsum(p[u]);
        int i = q * 32 + warp + 8 * u;
        if (lane == 0) g_xc[t * 256 + i] = eluf(p[u] + b1v[i]);
    }
    if (q == 0 && tid < 128) {
        float ma = m0[t * 2 + 0], mb = m0[t * 2 + 1];
        g_xc[t * 256 + 128 + tid] =
            eluf(ma * W1m[tid * 2] + mb * W1m[tid * 2 + 1] + b1m[tid]);
    }
    if (t == 0 && q == 0) {
        if (tid < 256) {
            g_h1[0][tid] = 0.f; g_h1[1][tid] = 0.f;
            g_h2[0][tid] = 0.f; g_h2[1][tid] = 0.f;
        }
        if (tid < NB2) g_slots[tid] = 0u;
    }
}

// ---------------- k1b: pre_low = WihL[:, :256] @ xc + bihL ----------------
__global__ void __launch_bounds__(256) k1b_pre(
    const float* __restrict__ WihL, const float* __restrict__ bihL)
{
    int t = blockIdx.x, s = blockIdx.y;
    int tid = threadIdx.x, warp = tid >> 5, lane = tid & 31;
    __shared__ __align__(16) float xc[256];
    if (tid < 256) xc[tid] = g_xc[t * 256 + tid];
    __syncthreads();
    const float4* xc4 = (const float4*)xc;

#pragma unroll
    for (int b = 0; b < 4; b++) {
        float p[4];
#pragma unroll
        for (int u = 0; u < 4; u++) {
            int g = s * 128 + warp + 8 * (b * 4 + u);
            const float4* w = (const float4*)(WihL + g * 512);
            p[u] = dot4(__ldg(w + lane), xc4[lane]) +
                   dot4(__ldg(w + lane + 32), xc4[lane + 32]);
        }
#pragma unroll
        for (int u = 0; u < 4; u++) {
            p[u] = warpsum(p[u]);
            int g = s * 128 + warp + 8 * (b * 4 + u);
            if (lane == 0) g_pre[t * 768 + g] = p[u] + bihL[g];
        }
    }
}

// ======= k2 cluster v9: warp-per-unit, f32x2 dots, no syncthreads in loop ====
// Warp w of CTA rank owns hidden unit j = rank*16 + w. It holds ALL 12 rows
// touching unit j in registers (packed f32x2):
//   A: WihL[j+256r, 256:512] (x=h2_old), WhhL[j+256r] (x=h1_old)
//   B: WihH[j+256r] (x=h1_new),          WhhH[j+256r] (x=h2_old)
// After warpsum all lanes hold all 6 sums -> gates computed redundantly per
// lane; lanes 0..15 each push h to cluster rank==lane (1 remote store/lane).
__global__ void __launch_bounds__(512, 1) k2_cluster(
    const float* __restrict__ WihL, const float* __restrict__ WhhL,
    const float* __restrict__ bhhLg,
    const float* __restrict__ WihH, const float* __restrict__ WhhH,
    const float* __restrict__ bihHg, const float* __restrict__ bhhHg)
{
    __shared__ __align__(16) float h1s[2][256], h2s[2][256];
    __shared__ float sbhhL[48], sbihH[48], sbhhH[48];

    int tid = threadIdx.x, warp = tid >> 5, lane = tid & 31;
    uint32_t rank;
    asm("mov.u32 %0, %%cluster_ctarank;" : "=r"(rank));
    int j0 = (int)rank * 16;
    int j = j0 + warp;                  // this warp's global hidden unit

    // ---- pack this lane's 12 weight rows into f32x2 registers ----
    ull wihL[3][4], whhL[3][4], wihH[3][4], whhH[3][4];
#pragma unroll
    for (int r = 0; r < 3; r++) {
        int row = j + 256 * r;
        const float4* pA = (const float4*)(WihL + row * 512 + 256);
        const float4* pB = (const float4*)(WhhL + row * 256);
        const float4* pC = (const float4*)(WihH + row * 256);
        const float4* pD = (const float4*)(WhhH + row * 256);
        float4 a0 = __ldg(pA + 2 * lane), a1 = __ldg(pA + 2 * lane + 1);
        float4 b0 = __ldg(pB + 2 * lane), b1 = __ldg(pB + 2 * lane + 1);
        float4 c0 = __ldg(pC + 2 * lane), c1 = __ldg(pC + 2 * lane + 1);
        float4 d0 = __ldg(pD + 2 * lane), d1 = __ldg(pD + 2 * lane + 1);
        wihL[r][0] = pack2(a0.x, a0.y); wihL[r][1] = pack2(a0.z, a0.w);
        wihL[r][2] = pack2(a1.x, a1.y); wihL[r][3] = pack2(a1.z, a1.w);
        whhL[r][0] = pack2(b0.x, b0.y); whhL[r][1] = pack2(b0.z, b0.w);
        whhL[r][2] = pack2(b1.x, b1.y); whhL[r][3] = pack2(b1.z, b1.w);
        wihH[r][0] = pack2(c0.x, c0.y); wihH[r][1] = pack2(c0.z, c0.w);
        wihH[r][2] = pack2(c1.x, c1.y); wihH[r][3] = pack2(c1.z, c1.w);
        whhH[r][0] = pack2(d0.x, d0.y); whhH[r][1] = pack2(d0.z, d0.w);
        whhH[r][2] = pack2(d1.x, d1.y); whhH[r][3] = pack2(d1.z, d1.w);
    }
    if (tid < 48) {
        int jj = tid / 3, r = tid % 3, row = j0 + jj + 256 * r;
        sbhhL[tid] = __ldg(bhhLg + row);
        sbihH[tid] = __ldg(bihHg + row);
        sbhhH[tid] = __ldg(bhhHg + row);
    }
    if (tid < 256) { h1s[0][tid] = 0.f; h2s[0][tid] = 0.f; }
    __syncthreads();
    CLUSTER_ARRIVE(); CLUSTER_WAIT();

    for (int t = 0; t < T_STEPS; t++) {
        int cb = t & 1, nb = cb ^ 1;

        // early pre loads (warp-uniform addresses -> broadcast L2 reqs);
        // consumed ~400 cyc later at the gates, latency hidden
        const float* pg = g_pre + t * 768 + j;
        float pr = __ldcg(pg), pz = __ldcg(pg + 256), pn = __ldcg(pg + 512);

        // ---- phase A: 6 dots for unit j's low cell ----
        float dih0, dih1, dih2, dhh0, dhh1, dhh2;
        {
            const float4* xp = (const float4*)h2s[cb];
            float4 a = xp[2 * lane], b = xp[2 * lane + 1];
            ull x0 = pack2(a.x, a.y), x1 = pack2(a.z, a.w);
            ull x2 = pack2(b.x, b.y), x3 = pack2(b.z, b.w);
            ull q0 = fmul2(wihL[0][0], x0), q1 = fmul2(wihL[1][0], x0),
                q2 = fmul2(wihL[2][0], x0);
            q0 = ffma2(wihL[0][1], x1, q0); q1 = ffma2(wihL[1][1], x1, q1);
            q2 = ffma2(wihL[2][1], x1, q2);
            q0 = ffma2(wihL[0][2], x2, q0); q1 = ffma2(wihL[1][2], x2, q1);
            q2 = ffma2(wihL[2][2], x2, q2);
            q0 = ffma2(wihL[0][3], x3, q0); q1 = ffma2(wihL[1][3], x3, q1);
            q2 = ffma2(wihL[2][3], x3, q2);
            dih0 = dotred(q0); dih1 = dotred(q1); dih2 = dotred(q2);
        }
        {
            const float4* xp = (const float4*)h1s[cb];
            float4 a = xp[2 * lane], b = xp[2 * lane + 1];
            ull x0 = pack2(a.x, a.y), x1 = pack2(a.z, a.w);
            ull x2 = pack2(b.x, b.y), x3 = pack2(b.z, b.w);
            ull q0 = fmul2(whhL[0][0], x0), q1 = fmul2(whhL[1][0], x0),
                q2 = fmul2(whhL[2][0], x0);
            q0 = ffma2(whhL[0][1], x1, q0); q1 = ffma2(whhL[1][1], x1, q1);
            q2 = ffma2(whhL[2][1], x1, q2);
            q0 = ffma2(whhL[0][2], x2, q0); q1 = ffma2(whhL[1][2], x2, q1);
            q2 = ffma2(whhL[2][2], x2, q2);
            q0 = ffma2(whhL[0][3], x3, q0); q1 = ffma2(whhL[1][3], x3, q1);
            q2 = ffma2(whhL[2][3], x3, q2);
            dhh0 = dotred(q0); dhh1 = dotred(q1); dhh2 = dotred(q2);
        }
        dih0 = warpsum(dih0); dih1 = warpsum(dih1); dih2 = warpsum(dih2);
        dhh0 = warpsum(dhh0); dhh1 = warpsum(dhh1); dhh2 = warpsum(dhh2);

        // gates (all lanes redundantly; smem broadcast reads)
        float h1n;
        {
            float blr = sbhhL[warp * 3 + 0], blz = sbhhL[warp * 3 + 1],
                  bln = sbhhL[warp * 3 + 2];
            float h1old = h1s[cb][j];
            float r_ = sigf(pr + dih0 + dhh0 + blr);
            float z_ = sigf(pz + dih1 + dhh1 + blz);
            float n_ = tanhf(pn + dih2 + r_ * (dhh2 + bln));
            h1n = (1.f - z_) * n_ + z_ * h1old;
        }
        if (lane == 0) g_Lout[t * 256 + j] = h1n;
        if (t == T_STEPS - 1) break;
        if (lane < 16)
            dsm_store(mapa_rk(s2u(&h1s[nb][j]), lane), h1n);
        CLUSTER_ARRIVE(); CLUSTER_WAIT();

        // ---- phase B: 6 dots for unit j's high cell ----
        float eih0, eih1, eih2, ehh0, ehh1, ehh2;
        {
            const float4* xp = (const float4*)h1s[nb];
            float4 a = xp[2 * lane], b = xp[2 * lane + 1];
            ull x0 = pack2(a.x, a.y), x1 = pack2(a.z, a.w);
            ull x2 = pack2(b.x, b.y), x3 = pack2(b.z, b.w);
            ull q0 = fmul2(wihH[0][0], x0), q1 = fmul2(wihH[1][0], x0),
                q2 = fmul2(wihH[2][0], x0);
            q0 = ffma2(wihH[0][1], x1, q0); q1 = ffma2(wihH[1][1], x1, q1);
            q2 = ffma2(wihH[2][1], x1, q2);
            q0 = ffma2(wihH[0][2], x2, q0); q1 = ffma2(wihH[1][2], x2, q1);
            q2 = ffma2(wihH[2][2], x2, q2);
            q0 = ffma2(wihH[0][3], x3, q0); q1 = ffma2(wihH[1][3], x3, q1);
            q2 = ffma2(wihH[2][3], x3, q2);
            eih0 = dotred(q0); eih1 = dotred(q1); eih2 = dotred(q2);
        }
        {
            const float4* xp = (const float4*)h2s[cb];
            float4 a = xp[2 * lane], b = xp[2 * lane + 1];
            ull x0 = pack2(a.x, a.y), x1 = pack2(a.z, a.w);
            ull x2 = pack2(b.x, b.y), x3 = pack2(b.z, b.w);
            ull q0 = fmul2(whhH[0][0], x0), q1 = fmul2(whhH[1][0], x0),
                q2 = fmul2(whhH[2][0], x0);
            q0 = ffma2(whhH[0][1], x1, q0); q1 = ffma2(whhH[1][1], x1, q1);
            q2 = ffma2(whhH[2][1], x1, q2);
            q0 = ffma2(whhH[0][2], x2, q0); q1 = ffma2(whhH[1][2], x2, q1);
            q2 = ffma2(whhH[2][2], x2, q2);
            q0 = ffma2(whhH[0][3], x3, q0); q1 = ffma2(whhH[1][3], x3, q1);
            q2 = ffma2(whhH[2][3], x3, q2);
            ehh0 = dotred(q0); ehh1 = dotred(q1); ehh2 = dotred(q2);
        }
        eih0 = warpsum(eih0); eih1 = warpsum(eih1); eih2 = warpsum(eih2);
        ehh0 = warpsum(ehh0); ehh1 = warpsum(ehh1); ehh2 = warpsum(ehh2);

        float h2n;
        {
            float bir = sbihH[warp * 3 + 0], biz = sbihH[warp * 3 + 1],
                  bin = sbihH[warp * 3 + 2];
            float bhr = sbhhH[warp * 3 + 0], bhz = sbhhH[warp * 3 + 1],
                  bhn = sbhhH[warp * 3 + 2];
            float h2old = h2s[cb][j];
            float r_ = sigf(eih0 + bir + ehh0 + bhr);
            float z_ = sigf(eih1 + biz + ehh1 + bhz);
            float n_ = tanhf(eih2 + bin + r_ * (ehh2 + bhn));
            h2n = (1.f - z_) * n_ + z_ * h2old;
        }
        if (lane < 16)
            dsm_store(mapa_rk(s2u(&h2s[nb][j]), lane), h2n);
        CLUSTER_ARRIVE(); CLUSTER_WAIT();
    }

    // teardown: no CTA exits while peers' remote stores may be in flight
    CLUSTER_ARRIVE(); CLUSTER_WAIT();
}

// ---------------- k2 fallback: L2-flag scan (proven) ----------------
extern __shared__ float smw[];
__global__ void __launch_bounds__(256, 1) k2_scan(
    const float* __restrict__ WihL, const float* __restrict__ WhhL,
    const float* __restrict__ bhhLg,
    const float* __restrict__ WihH, const float* __restrict__ WhhH,
    const float* __restrict__ bihHg, const float* __restrict__ bhhHg)
{
    float* wA = smw;
    float* wB = smw + 48 * 256;
    __shared__ float dots[48], preS[24], bA[24], bB1[24], bB2[24];

    int tid = threadIdx.x, warp = tid >> 5, lane = tid & 31, cta = blockIdx.x;
    int j0 = cta * 8;
    {
        int r4 = tid >> 6, c = tid & 63;
        for (int d0 = 0; d0 < 48; d0 += 4) {
            int d = d0 + r4;
            int jj = (d % 24) / 3, r = d % 3, grow = j0 + jj + 256 * r;
            const float4* srcA = (d < 24)
                ? (const float4*)(WihL + grow * 512 + 256)
                : (const float4*)(WhhL + grow * 256);
            ((float4*)(wA + d * 256))[c] = __ldg(srcA + c);
            const float4* srcB = (d < 24)
                ? (const float4*)(WihH + grow * 256)
                : (const float4*)(WhhH + grow * 256);
            ((float4*)(wB + d * 256))[c] = __ldg(srcB + c);
        }
    }
    if (tid < 24) {
        int jj = tid / 3, r = tid % 3, grow = j0 + jj + 256 * r;
        bA[tid] = bhhLg[grow]; bB1[tid] = bihHg[grow]; bB2[tid] = bhhHg[grow];
    }
    __syncthreads();

    for (int t = 0; t < T_STEPS; t++) {
        if (tid < 24)
            preS[tid] = __ldg(&g_pre[t * 768 + j0 + (tid / 3) + 256 * (tid % 3)]);
        const float* h1r = g_h1[t & 1];
        const float* h2r = g_h2[t & 1];
        float* h1w = g_h1[(t & 1) ^ 1];
        float* h2w = g_h2[(t & 1) ^ 1];
        float4 h1a = __ldcg((const float4*)h1r + lane);
        float4 h1b = __ldcg((const float4*)h1r + lane + 32);
        float4 h2a = __ldcg((const float4*)h2r + lane);
        float4 h2b = __ldcg((const float4*)h2r + lane + 32);
        {
            float p[6];
#pragma unroll
            for (int i = 0; i < 6; i++) {
                const float4* w = (const float4*)(wA + (warp + 8 * i) * 256);
                float4 xa = (i < 3) ? h2a : h1a, xb = (i < 3) ? h2b : h1b;
                p[i] = dot4(w[lane], xa) + dot4(w[lane + 32], xb);
            }
#pragma unroll
            for (int i = 0; i < 6; i++) p[i] = warpsum(p[i]);
            if (lane == 0)
#pragma unroll
                for (int i = 0; i < 6; i++) dots[warp + 8 * i] = p[i];
        }
        __syncthreads();
        if (tid < 8) {
            int jj = tid, j = j0 + jj;
            float r_ = sigf(preS[jj*3+0] + dots[jj*3+0] + dots[24+jj*3+0] + bA[jj*3+0]);
            float z_ = sigf(preS[jj*3+1] + dots[jj*3+1] + dots[24+jj*3+1] + bA[jj*3+1]);
            float n_ = tanhf(preS[jj*3+2] + dots[jj*3+2] + r_*(dots[24+jj*3+2] + bA[jj*3+2]));
            float h1n = (1.f - z_) * n_ + z_ * __ldcg(h1r + j);
            h1w[j] = h1n;
            g_Lout[t * 256 + j] = h1n;
        }
        if (t == T_STEPS - 1) break;
        gridbar(2 * t + 1, tid, cta);
        float4 na = __ldcg((const float4*)h1w + lane);
        float4 nb4 = __ldcg((const float4*)h1w + lane + 32);
        {
            float p[6];
#pragma unroll
            for (int i = 0; i < 6; i++) {
                const float4* w = (const float4*)(wB + (warp + 8 * i) * 256);
                float4 xa = (i < 3) ? na : h2a, xb = (i < 3) ? nb4 : h2b;
                p[i] = dot4(w[lane], xa) + dot4(w[lane + 32], xb);
            }
#pragma unroll
            for (int i = 0; i < 6; i++) p[i] = warpsum(p[i]);
            if (lane == 0)
#pragma unroll
                for (int i = 0; i < 6; i++) dots[warp + 8 * i] = p[i];
        }
        __syncthreads();
        if (tid < 8) {
            int jj = tid, j = j0 + jj;
            float r_ = sigf(dots[jj*3+0] + bB1[jj*3+0] + dots[24+jj*3+0] + bB2[jj*3+0]);
            float z_ = sigf(dots[jj*3+1] + bB1[jj*3+1] + dots[24+jj*3+1] + bB2[jj*3+1]);
            float n_ = tanhf(dots[jj*3+2] + bB1[jj*3+2] + r_*(dots[24+jj*3+2] + bB2[jj*3+2]));
            h2w[j] = (1.f - z_) * n_ + z_ * __ldcg(h2r + j);
        }
        gridbar(2 * t + 2, tid, cta);
    }
}

// ---------------- k3: output heads ----------------
__global__ void __launch_bounds__(256) k3_out(
    const float* __restrict__ W2v, const float* __restrict__ b2v,
    const float* __restrict__ W2m, const float* __restrict__ b2m,
    float* __restrict__ out)
{
    int t = blockIdx.x, s = blockIdx.y;
    int tid = threadIdx.x, warp = tid >> 5, lane = tid & 31;
    __shared__ __align__(16) float fv[128], fm[128];
    if (tid < 128) fv[tid] = eluf(g_Lout[t * 256 + tid]);
    else           fm[tid - 128] = eluf(g_Lout[t * 256 + tid]);
    __syncthreads();

    const float4* fv4 = (const float4*)fv;
#pragma unroll
    for (int b = 0; b < 3; b++) {
        float p[4];
#pragma unroll
        for (int u = 0; u < 4; u++) {
            int i = s * 96 + warp + 8 * (b * 4 + u);
            p[u] = dot4(__ldg((const float4*)(W2v + i * 128) + lane), fv4[lane]);
        }
#pragma unroll
        for (int u = 0; u < 4; u++) {
            p[u] = warpsum(p[u]);
            int i = s * 96 + warp + 8 * (b * 4 + u);
            if (lane == 0) out[t * 768 + i] = sigf(p[u] + b2v[i]);
        }
    }
    if (s == 0 && warp < 2) {
        const float4* fm4 = (const float4*)fm;
        float v = dot4(__ldg((const float4*)(W2m + warp * 128) + lane), fm4[lane]);
        v = warpsum(v);
        if (lane == 0) out[T_STEPS * 768 + t * 2 + warp] = tanhf(v + b2m[warp]);
    }
}

// ---------------- launch ----------------
extern "C" void kernel_launch(void* const* d_in, const int* in_sizes, int n_in,
                              void* d_out, int out_size) {
    const float* v0   = (const float*)d_in[0];
    const float* m0   = (const float*)d_in[1];
    const float* W1v  = (const float*)d_in[2];
    const float* b1v  = (const float*)d_in[3];
    const float* W1m  = (const float*)d_in[4];
    const float* b1m  = (const float*)d_in[5];
    const float* WihL = (const float*)d_in[6];
    const float* WhhL = (const float*)d_in[7];
    const float* bihL = (const float*)d_in[8];
    const float* bhhL = (const float*)d_in[9];
    const float* WihH = (const float*)d_in[10];
    const float* WhhH = (const float*)d_in[11];
    const float* bihH = (const float*)d_in[12];
    const float* bhhH = (const float*)d_in[13];
    const float* W2v  = (const float*)d_in[14];
    const float* b2v  = (const float*)d_in[15];
    const float* W2m  = (const float*)d_in[16];
    const float* b2m  = (const float*)d_in[17];
    float* out = (float*)d_out;

    const int FB_SMEM = 96 * 256 * 4;
    cudaFuncSetAttribute(k2_cluster, cudaFuncAttributeNonPortableClusterSizeAllowed, 1);
    cudaFuncSetAttribute(k2_scan, cudaFuncAttributeMaxDynamicSharedMemorySize, FB_SMEM);

    k1a_feat<<<dim3(T_STEPS, 4), 256>>>(v0, m0, W1v, b1v, W1m, b1m);
    k1b_pre <<<dim3(T_STEPS, 6), 256>>>(WihL, bihL);

    cudaLaunchConfig_t cfg = {};
    cfg.gridDim = dim3(CL, 1, 1);
    cfg.blockDim = dim3(512, 1, 1);
    cfg.dynamicSmemBytes = 0;
    cfg.stream = 0;
    cudaLaunchAttribute attrs[1];
    attrs[0].id = cudaLaunchAttributeClusterDimension;
    attrs[0].val.clusterDim = {CL, 1, 1};
    cfg.attrs = attrs;
    cfg.numAttrs = 1;
    cudaError_t st = cudaLaunchKernelEx(&cfg, k2_cluster,
                                        WihL, WhhL, bhhL, WihH, WhhH, bihH, bhhH);
    if (st != cudaSuccess) {
        (void)cudaGetLastError();  // clear; deterministic proven fallback
        k2_scan<<<NB2, 256, FB_SMEM>>>(WihL, WhhL, bhhL, WihH, WhhH, bihH, bhhH);
    }

    k3_out<<<dim3(T_STEPS, 8), 256>>>(W2v, b2v, W2m, b2m, out);
}

// round 10
// speedup vs baseline: 2.2529x; 2.2529x over previous
#include <cuda_runtime.h>
#include <cstdint>

#define T_STEPS 50
#define NB2 32          // fallback scan CTAs
#define CL 16           // cluster CTAs; each owns 16 of 256 hidden units

// ---------------- scratch (device globals; no allocation) ----------------
__device__ float    g_pre[T_STEPS * 768];   // Wih_low[:, :256]@x_t + bih_low
__device__ float    g_xc [T_STEPS * 256];   // concat(f_v, f_m)
__device__ float    g_Lout[T_STEPS * 256];  // h1 per step
__device__ float    g_h1[2][256];           // fallback state
__device__ float    g_h2[2][256];
__device__ unsigned g_slots[NB2];           // fallback barrier slots

// ---------------- helpers ----------------
__device__ __forceinline__ float warpsum(float v) {
    v += __shfl_xor_sync(0xffffffffu, v, 16);
    v += __shfl_xor_sync(0xffffffffu, v, 8);
    v += __shfl_xor_sync(0xffffffffu, v, 4);
    v += __shfl_xor_sync(0xffffffffu, v, 2);
    v += __shfl_xor_sync(0xffffffffu, v, 1);
    return v;
}
__device__ __forceinline__ float eluf(float x) { return x > 0.f ? x : expm1f(x); }
__device__ __forceinline__ float sigf(float x) { return 1.f / (1.f + expf(-x)); }
__device__ __forceinline__ float dot4(float4 a, float4 b) {
    return a.x * b.x + a.y * b.y + a.z * b.z + a.w * b.w;
}
__device__ __forceinline__ uint32_t s2u(const void* p) {
    uint32_t a;
    asm("{ .reg .u64 t; cvta.to.shared.u64 t, %1; cvt.u32.u64 %0, t; }"
        : "=r"(a) : "l"(p));
    return a;
}
__device__ __forceinline__ uint32_t mapa_rk(uint32_t laddr, int rk) {
    uint32_t ra;
    asm volatile("mapa.shared::cluster.u32 %0, %1, %2;"
                 : "=r"(ra) : "r"(laddr), "r"(rk));
    return ra;
}
// one atomic 8B push: {value bits, epoch}
__device__ __forceinline__ void dsm_store2(uint32_t ra, uint32_t vb, uint32_t ep) {
    asm volatile("st.shared::cluster.v2.u32 [%0], {%1, %2};"
                 :: "r"(ra), "r"(vb), "r"(ep) : "memory");
}
// spin on local mailbox word until epoch matches; return value
__device__ __forceinline__ float poll_mb(uint32_t addr, uint32_t want) {
    uint32_t v, e;
    do {
        asm volatile("ld.volatile.shared.v2.u32 {%0, %1}, [%2];"
                     : "=r"(v), "=r"(e) : "r"(addr));
    } while (e != want);
    return __uint_as_float(v);
}
#define CLUSTER_ARRIVE() asm volatile("barrier.cluster.arrive.aligned;" ::: "memory")
#define CLUSTER_WAIT()   asm volatile("barrier.cluster.wait.aligned;"   ::: "memory")

// fallback epoch barrier (proven)
__device__ __forceinline__ void gridbar(unsigned epoch, int tid, int cta) {
    __syncthreads();
    if (tid == 0)
        asm volatile("st.release.gpu.global.u32 [%0], %1;"
                     :: "l"(g_slots + cta), "r"(epoch) : "memory");
    if (tid < 32) {
        unsigned v;
        do {
            asm volatile("ld.acquire.gpu.global.u32 %0, [%1];"
                         : "=r"(v) : "l"(g_slots + tid) : "memory");
        } while (__any_sync(0xffffffffu, v < epoch));
    }
    __syncthreads();
}

// ---------------- k1a: f_v / f_m -> g_xc, + fallback state init ----------------
__global__ void __launch_bounds__(256) k1a_feat(
    const float* __restrict__ v0, const float* __restrict__ m0,
    const float* __restrict__ W1v, const float* __restrict__ b1v,
    const float* __restrict__ W1m, const float* __restrict__ b1m)
{
    int t = blockIdx.x, q = blockIdx.y;
    int tid = threadIdx.x, warp = tid >> 5, lane = tid & 31;
    __shared__ __align__(16) float xv[768];
    for (int i = tid; i < 768; i += 256) xv[i] = v0[t * 768 + i];
    __syncthreads();

    const float4* xv4 = (const float4*)xv;
    float p[4];
#pragma unroll
    for (int u = 0; u < 4; u++) {
        int i = q * 32 + warp + 8 * u;
        const float4* w = (const float4*)(W1v + i * 768);
        float s = 0.f;
#pragma unroll
        for (int k = 0; k < 6; k++)
            s += dot4(__ldg(w + lane + 32 * k), xv4[lane + 32 * k]);
        p[u] = s;
    }
#pragma unroll
    for (int u = 0; u < 4; u++) {
        p[u] = warpsum(p[u]);
        int i = q * 32 + warp + 8 * u;
        if (lane == 0) g_xc[t * 256 + i] = eluf(p[u] + b1v[i]);
    }
    if (q == 0 && tid < 128) {
        float ma = m0[t * 2 + 0], mb = m0[t * 2 + 1];
        g_xc[t * 256 + 128 + tid] =
            eluf(ma * W1m[tid * 2] + mb * W1m[tid * 2 + 1] + b1m[tid]);
    }
    if (t == 0 && q == 0) {
        if (tid < 256) {
            g_h1[0][tid] = 0.f; g_h1[1][tid] = 0.f;
            g_h2[0][tid] = 0.f; g_h2[1][tid] = 0.f;
        }
        if (tid < NB2) g_slots[tid] = 0u;
    }
}

// ---------------- k1b: pre_low = WihL[:, :256] @ xc + bihL ----------------
__global__ void __launch_bounds__(256) k1b_pre(
    const float* __restrict__ WihL, const float* __restrict__ bihL)
{
    int t = blockIdx.x, s = blockIdx.y;
    int tid = threadIdx.x, warp = tid >> 5, lane = tid & 31;
    __shared__ __align__(16) float xc[256];
    if (tid < 256) xc[tid] = g_xc[t * 256 + tid];
    __syncthreads();
    const float4* xc4 = (const float4*)xc;

#pragma unroll
    for (int b = 0; b < 4; b++) {
        float p[4];
#pragma unroll
        for (int u = 0; u < 4; u++) {
            int g = s * 128 + warp + 8 * (b * 4 + u);
            const float4* w = (const float4*)(WihL + g * 512);
            p[u] = dot4(__ldg(w + lane), xc4[lane]) +
                   dot4(__ldg(w + lane + 32), xc4[lane + 32]);
        }
#pragma unroll
        for (int u = 0; u < 4; u++) {
            p[u] = warpsum(p[u]);
            int g = s * 128 + warp + 8 * (b * 4 + u);
            if (lane == 0) g_pre[t * 768 + g] = p[u] + bihL[g];
        }
    }
}

// ======= k2 cluster v10: r7 compute + epoch-mailbox sync (no barriers) =======
// Warp w: m_ = w>>3 (matrix), idx = w&7; combos c = idx*6+k = jj*3+r.
// Phase A: m=0 -> WihL[row,256:512].h2_old ; m=1 -> WhhL[row].h1_old
// Phase B: m=0 -> WihH[row].h1_new         ; m=1 -> WhhH[row].h2_old
// State in compact h1c/h2c; cross-CTA exchange via double-buffered 8B
// {value, epoch} mailboxes; consumers spin locally, then copy to compact.
__global__ void __launch_bounds__(512, 1) k2_cluster(
    const float* __restrict__ WihL, const float* __restrict__ WhhL,
    const float* __restrict__ bhhLg,
    const float* __restrict__ WihH, const float* __restrict__ WhhH,
    const float* __restrict__ bihHg, const float* __restrict__ bhhHg)
{
    __shared__ __align__(16) float h1c[256], h2c[256];
    __shared__ __align__(8) uint2 mb1[2][256], mb2[2][256];
    __shared__ float dots[96], sbhhL[48], sbihH[48], sbhhH[48];

    int tid = threadIdx.x, warp = tid >> 5, lane = tid & 31;
    int m_ = warp >> 3, idx = warp & 7;
    uint32_t rank;
    asm("mov.u32 %0, %%cluster_ctarank;" : "=r"(rank));
    int j0 = (int)rank * 16;

    // ---- register weights (r7-proven layout) ----
    float4 wA[6][2], wB[6][2];
#pragma unroll
    for (int k = 0; k < 6; k++) {
        int c = idx * 6 + k, jj = c / 3, r = c % 3;
        int row = j0 + jj + 256 * r;
        const float4* pa = m_ ? (const float4*)(WhhL + row * 256)
                              : (const float4*)(WihL + row * 512 + 256);
        const float4* pb = m_ ? (const float4*)(WhhH + row * 256)
                              : (const float4*)(WihH + row * 256);
        wA[k][0] = __ldg(pa + lane * 2);  wA[k][1] = __ldg(pa + lane * 2 + 1);
        wB[k][0] = __ldg(pb + lane * 2);  wB[k][1] = __ldg(pb + lane * 2 + 1);
    }
    if (tid < 48) {
        int jj = tid / 3, r = tid % 3, row = j0 + jj + 256 * r;
        sbhhL[tid] = __ldg(bhhLg + row);
        sbihH[tid] = __ldg(bihHg + row);
        sbhhH[tid] = __ldg(bhhHg + row);
    }
    if (tid < 256) {
        h1c[tid] = 0.f;  h2c[tid] = 0.f;
        mb1[0][tid] = make_uint2(0u, 0u);  mb1[1][tid] = make_uint2(0u, 0u);
        mb2[0][tid] = make_uint2(0u, 0u);  mb2[1][tid] = make_uint2(0u, 0u);
    }

    // remote mailbox addrs (this thread sends element j0+be to rank brk)
    int be = tid & 15, brk = tid >> 4;
    uint32_t raM1[2], raM2[2], pl1[2], pl2[2];
    if (tid < 256) {
#pragma unroll
        for (int b = 0; b < 2; b++) {
            raM1[b] = mapa_rk(s2u(&mb1[b][j0 + be]), brk);
            raM2[b] = mapa_rk(s2u(&mb2[b][j0 + be]), brk);
            pl1[b]  = s2u(&mb1[b][tid]);     // local poll addrs
            pl2[b]  = s2u(&mb2[b][tid]);
        }
    }
    __syncthreads();
    CLUSTER_ARRIVE(); CLUSTER_WAIT();    // all inits visible before any push

    for (int t = 0; t < T_STEPS; t++) {
        int cb = t & 1, nb = cb ^ 1;

        // ---- phase A wait: h2(t) arrives in mb2[cb] with epoch t ----
        if (tid < 256)
            h2c[tid] = poll_mb(pl2[cb], (uint32_t)t);
        __syncthreads();

        // gate-side pre loads (consumed after dots; latency hidden)
        float pr, pz, pn;
        if (tid < 16) {
            const float* pg = g_pre + t * 768 + j0 + tid;
            pr = __ldcg(pg); pz = __ldcg(pg + 256); pn = __ldcg(pg + 512);
        }

        // ---- phase A dots ----
        {
            const float4* xp = (const float4*)(m_ ? h1c : h2c);
            float4 xlo = xp[lane * 2], xhi = xp[lane * 2 + 1];
            float a[6];
#pragma unroll
            for (int k = 0; k < 6; k++)
                a[k] = dot4(wA[k][0], xlo) + dot4(wA[k][1], xhi);
#pragma unroll
            for (int k = 0; k < 6; k++) a[k] = warpsum(a[k]);
            if (lane == 0) {
#pragma unroll
                for (int k = 0; k < 6; k++) dots[m_ * 48 + idx * 6 + k] = a[k];
            }
        }
        __syncthreads();
        if (tid < 16) {
            int jj = tid, j = j0 + jj;
            float r_ = sigf(pr + dots[jj * 3 + 0] +
                            dots[48 + jj * 3 + 0] + sbhhL[jj * 3 + 0]);
            float z_ = sigf(pz + dots[jj * 3 + 1] +
                            dots[48 + jj * 3 + 1] + sbhhL[jj * 3 + 1]);
            float n_ = tanhf(pn + dots[jj * 3 + 2] +
                             r_ * (dots[48 + jj * 3 + 2] + sbhhL[jj * 3 + 2]));
            float h1n = (1.f - z_) * n_ + z_ * h1c[j];
            g_Lout[t * 256 + j] = h1n;
            h1c[j] = h1n;
        }
        if (t == T_STEPS - 1) break;
        __syncthreads();

        // push h1(t+1): one 8B store per (element, rank)
        if (tid < 256)
            dsm_store2(raM1[nb], __float_as_uint(h1c[j0 + be]), (uint32_t)(t + 1));

        // ---- phase B wait: h1(t+1) in mb1[nb] with epoch t+1 ----
        if (tid < 256)
            h1c[tid] = poll_mb(pl1[nb], (uint32_t)(t + 1));
        __syncthreads();

        // ---- phase B dots ----
        {
            const float4* xp = (const float4*)(m_ ? h2c : h1c);
            float4 xlo = xp[lane * 2], xhi = xp[lane * 2 + 1];
            float a[6];
#pragma unroll
            for (int k = 0; k < 6; k++)
                a[k] = dot4(wB[k][0], xlo) + dot4(wB[k][1], xhi);
#pragma unroll
            for (int k = 0; k < 6; k++) a[k] = warpsum(a[k]);
            if (lane == 0) {
#pragma unroll
                for (int k = 0; k < 6; k++) dots[m_ * 48 + idx * 6 + k] = a[k];
            }
        }
        __syncthreads();
        if (tid < 16) {
            int jj = tid, j = j0 + jj;
            float r_ = sigf(dots[jj * 3 + 0] + sbihH[jj * 3 + 0] +
                            dots[48 + jj * 3 + 0] + sbhhH[jj * 3 + 0]);
            float z_ = sigf(dots[jj * 3 + 1] + sbihH[jj * 3 + 1] +
                            dots[48 + jj * 3 + 1] + sbhhH[jj * 3 + 1]);
            float n_ = tanhf(dots[jj * 3 + 2] + sbihH[jj * 3 + 2] +
                             r_ * (dots[48 + jj * 3 + 2] + sbhhH[jj * 3 + 2]));
            float h2n = (1.f - z_) * n_ + z_ * h2c[j];
            h2c[j] = h2n;
        }
        __syncthreads();

        // push h2(t+1); consumed by next iteration's phase A poll
        if (tid < 256)
            dsm_store2(raM2[nb], __float_as_uint(h2c[j0 + be]), (uint32_t)(t + 1));
    }

    // teardown: by now every CTA observed all stores targeting it (polls
    // passed); single rendezvous before exit for cluster-lifetime safety.
    CLUSTER_ARRIVE(); CLUSTER_WAIT();
}

// ---------------- k2 fallback: L2-flag scan (proven) ----------------
extern __shared__ float smw[];
__global__ void __launch_bounds__(256, 1) k2_scan(
    const float* __restrict__ WihL, const float* __restrict__ WhhL,
    const float* __restrict__ bhhLg,
    const float* __restrict__ WihH, const float* __restrict__ WhhH,
    const float* __restrict__ bihHg, const float* __restrict__ bhhHg)
{
    float* wA = smw;
    float* wB = smw + 48 * 256;
    __shared__ float dots[48], preS[24], bA[24], bB1[24], bB2[24];

    int tid = threadIdx.x, warp = tid >> 5, lane = tid & 31, cta = blockIdx.x;
    int j0 = cta * 8;
    {
        int r4 = tid >> 6, c = tid & 63;
        for (int d0 = 0; d0 < 48; d0 += 4) {
            int d = d0 + r4;
            int jj = (d % 24) / 3, r = d % 3, grow = j0 + jj + 256 * r;
            const float4* srcA = (d < 24)
                ? (const float4*)(WihL + grow * 512 + 256)
                : (const float4*)(WhhL + grow * 256);
            ((float4*)(wA + d * 256))[c] = __ldg(srcA + c);
            const float4* srcB = (d < 24)
                ? (const float4*)(WihH + grow * 256)
                : (const float4*)(WhhH + grow * 256);
            ((float4*)(wB + d * 256))[c] = __ldg(srcB + c);
        }
    }
    if (tid < 24) {
        int jj = tid / 3, r = tid % 3, grow = j0 + jj + 256 * r;
        bA[tid] = bhhLg[grow]; bB1[tid] = bihHg[grow]; bB2[tid] = bhhHg[grow];
    }
    __syncthreads();

    for (int t = 0; t < T_STEPS; t++) {
        if (tid < 24)
            preS[tid] = __ldg(&g_pre[t * 768 + j0 + (tid / 3) + 256 * (tid % 3)]);
        const float* h1r = g_h1[t & 1];
        const float* h2r = g_h2[t & 1];
        float* h1w = g_h1[(t & 1) ^ 1];
        float* h2w = g_h2[(t & 1) ^ 1];
        float4 h1a = __ldcg((const float4*)h1r + lane);
        float4 h1b = __ldcg((const float4*)h1r + lane + 32);
        float4 h2a = __ldcg((const float4*)h2r + lane);
        float4 h2b = __ldcg((const float4*)h2r + lane + 32);
        {
            float p[6];
#pragma unroll
            for (int i = 0; i < 6; i++) {
                const float4* w = (const float4*)(wA + (warp + 8 * i) * 256);
                float4 xa = (i < 3) ? h2a : h1a, xb = (i < 3) ? h2b : h1b;
                p[i] = dot4(w[lane], xa) + dot4(w[lane + 32], xb);
            }
#pragma unroll
            for (int i = 0; i < 6; i++) p[i] = warpsum(p[i]);
            if (lane == 0)
#pragma unroll
                for (int i = 0; i < 6; i++) dots[warp + 8 * i] = p[i];
        }
        __syncthreads();
        if (tid < 8) {
            int jj = tid, j = j0 + jj;
            float r_ = sigf(preS[jj*3+0] + dots[jj*3+0] + dots[24+jj*3+0] + bA[jj*3+0]);
            float z_ = sigf(preS[jj*3+1] + dots[jj*3+1] + dots[24+jj*3+1] + bA[jj*3+1]);
            float n_ = tanhf(preS[jj*3+2] + dots[jj*3+2] + r_*(dots[24+jj*3+2] + bA[jj*3+2]));
            float h1n = (1.f - z_) * n_ + z_ * __ldcg(h1r + j);
            h1w[j] = h1n;
            g_Lout[t * 256 + j] = h1n;
        }
        if (t == T_STEPS - 1) break;
        gridbar(2 * t + 1, tid, cta);
        float4 na = __ldcg((const float4*)h1w + lane);
        float4 nb4 = __ldcg((const float4*)h1w + lane + 32);
        {
            float p[6];
#pragma unroll
            for (int i = 0; i < 6; i++) {
                const float4* w = (const float4*)(wB + (warp + 8 * i) * 256);
                float4 xa = (i < 3) ? na : h2a, xb = (i < 3) ? nb4 : h2b;
                p[i] = dot4(w[lane], xa) + dot4(w[lane + 32], xb);
            }
#pragma unroll
            for (int i = 0; i < 6; i++) p[i] = warpsum(p[i]);
            if (lane == 0)
#pragma unroll
                for (int i = 0; i < 6; i++) dots[warp + 8 * i] = p[i];
        }
        __syncthreads();
        if (tid < 8) {
            int jj = tid, j = j0 + jj;
            float r_ = sigf(dots[jj*3+0] + bB1[jj*3+0] + dots[24+jj*3+0] + bB2[jj*3+0]);
            float z_ = sigf(dots[jj*3+1] + bB1[jj*3+1] + dots[24+jj*3+1] + bB2[jj*3+1]);
            float n_ = tanhf(dots[jj*3+2] + bB1[jj*3+2] + r_*(dots[24+jj*3+2] + bB2[jj*3+2]));
            h2w[j] = (1.f - z_) * n_ + z_ * __ldcg(h2r + j);
        }
        gridbar(2 * t + 2, tid, cta);
    }
}

// ---------------- k3: output heads ----------------
__global__ void __launch_bounds__(256) k3_out(
    const float* __restrict__ W2v, const float* __restrict__ b2v,
    const float* __restrict__ W2m, const float* __restrict__ b2m,
    float* __restrict__ out)
{
    int t = blockIdx.x, s = blockIdx.y;
    int tid = threadIdx.x, warp = tid >> 5, lane = tid & 31;
    __shared__ __align__(16) float fv[128], fm[128];
    if (tid < 128) fv[tid] = eluf(g_Lout[t * 256 + tid]);
    else           fm[tid - 128] = eluf(g_Lout[t * 256 + tid]);
    __syncthreads();

    const float4* fv4 = (const float4*)fv;
#pragma unroll
    for (int b = 0; b < 3; b++) {
        float p[4];
#pragma unroll
        for (int u = 0; u < 4; u++) {
            int i = s * 96 + warp + 8 * (b * 4 + u);
            p[u] = dot4(__ldg((const float4*)(W2v + i * 128) + lane), fv4[lane]);
        }
#pragma unroll
        for (int u = 0; u < 4; u++) {
            p[u] = warpsum(p[u]);
            int i = s * 96 + warp + 8 * (b * 4 + u);
            if (lane == 0) out[t * 768 + i] = sigf(p[u] + b2v[i]);
        }
    }
    if (s == 0 && warp < 2) {
        const float4* fm4 = (const float4*)fm;
        float v = dot4(__ldg((const float4*)(W2m + warp * 128) + lane), fm4[lane]);
        v = warpsum(v);
        if (lane == 0) out[T_STEPS * 768 + t * 2 + warp] = tanhf(v + b2m[warp]);
    }
}

// ---------------- launch ----------------
extern "C" void kernel_launch(void* const* d_in, const int* in_sizes, int n_in,
                              void* d_out, int out_size) {
    const float* v0   = (const float*)d_in[0];
    const float* m0   = (const float*)d_in[1];
    const float* W1v  = (const float*)d_in[2];
    const float* b1v  = (const float*)d_in[3];
    const float* W1m  = (const float*)d_in[4];
    const float* b1m  = (const float*)d_in[5];
    const float* WihL = (const float*)d_in[6];
    const float* WhhL = (const float*)d_in[7];
    const float* bihL = (const float*)d_in[8];
    const float* bhhL = (const float*)d_in[9];
    const float* WihH = (const float*)d_in[10];
    const float* WhhH = (const float*)d_in[11];
    const float* bihH = (const float*)d_in[12];
    const float* bhhH = (const float*)d_in[13];
    const float* W2v  = (const float*)d_in[14];
    const float* b2v  = (const float*)d_in[15];
    const float* W2m  = (const float*)d_in[16];
    const float* b2m  = (const float*)d_in[17];
    float* out = (float*)d_out;

    const int FB_SMEM = 96 * 256 * 4;
    cudaFuncSetAttribute(k2_cluster, cudaFuncAttributeNonPortableClusterSizeAllowed, 1);
    cudaFuncSetAttribute(k2_scan, cudaFuncAttributeMaxDynamicSharedMemorySize, FB_SMEM);

    k1a_feat<<<dim3(T_STEPS, 4), 256>>>(v0, m0, W1v, b1v, W1m, b1m);
    k1b_pre <<<dim3(T_STEPS, 6), 256>>>(WihL, bihL);

    cudaLaunchConfig_t cfg = {};
    cfg.gridDim = dim3(CL, 1, 1);
    cfg.blockDim = dim3(512, 1, 1);
    cfg.dynamicSmemBytes = 0;
    cfg.stream = 0;
    cudaLaunchAttribute attrs[1];
    attrs[0].id = cudaLaunchAttributeClusterDimension;
    attrs[0].val.clusterDim = {CL, 1, 1};
    cfg.attrs = attrs;
    cfg.numAttrs = 1;
    cudaError_t st = cudaLaunchKernelEx(&cfg, k2_cluster,
                                        WihL, WhhL, bhhL, WihH, WhhH, bihH, bhhH);
    if (st != cudaSuccess) {
        (void)cudaGetLastError();  // clear; deterministic proven fallback
        k2_scan<<<NB2, 256, FB_SMEM>>>(WihL, WhhL, bhhL, WihH, WhhH, bihH, bhhH);
    }

    k3_out<<<dim3(T_STEPS, 8), 256>>>(W2v, b2v, W2m, b2m, out);
}